// round 13
// baseline (speedup 1.0000x reference)
#include <cuda_runtime.h>
#include <cuda_fp16.h>
#include <cstdint>
#include <math.h>

#define NHID   1024
#define NLAY   4
#define NST    64
#define TSTEPS 101
#define NUNITS (NLAY*NHID)            // 4096
#define ROWLEN 2048                   // packed gate row: [Whh(1024) | Wih(1024)] halfs
#define NCTA     148
#define GCTAS    37                   // CTAs per layer group
#define NTHREADS 896                  // 28 warps

// smem layout in uint4 units:
//   [0, 256)        staging: [h_l(t-1) (128 u4) | x (128 u4)]
//   [256, 14080)    resident weights (group 0: 27 x 512 u4; groups 1-3: 13 x 1024 u4)
#define SW_U4 256
#define SMEM_TOTAL (14080*16)         // 225280 bytes

#define OUT_STATES 0
#define OUT_PROBS  (TSTEPS*NST)              // 6464
#define OUT_SAMP   (OUT_PROBS + TSTEPS*2)    // 6666

#define H2(v,k) (((const __half2*)&(v))[k])

// ---- persistent device state ----
__device__ __align__(128) __half g_wpack[(size_t)NUNITS * 4 * ROWLEN]; // 64 MB
__device__ float  g_bias[NLAY*4*NHID];
__device__ __align__(16) __half g_ws[NST*NHID];
__device__ __align__(16) __half g_hout[2][NLAY][NHID];
__device__ __align__(128) unsigned g_pinit;     // init barrier counter (monotonic)
__device__ __align__(128) unsigned g_c0;        // per-group step counters (monotonic)
__device__ __align__(128) unsigned g_c1;
__device__ __align__(128) unsigned g_c2;
__device__ __align__(128) unsigned g_c3;

// ---- math helpers (round-4 verbatim) ----
__device__ __forceinline__ float hdot16(uint4 wa, uint4 wb, uint4 xa, uint4 xb) {
    __half2 h = __hmul2(H2(wa,0), H2(xa,0));
    h = __hfma2(H2(wa,1), H2(xa,1), h);
    h = __hfma2(H2(wa,2), H2(xa,2), h);
    h = __hfma2(H2(wa,3), H2(xa,3), h);
    h = __hfma2(H2(wb,0), H2(xb,0), h);
    h = __hfma2(H2(wb,1), H2(xb,1), h);
    h = __hfma2(H2(wb,2), H2(xb,2), h);
    h = __hfma2(H2(wb,3), H2(xb,3), h);
    return __low2float(h) + __high2float(h);
}

__device__ __forceinline__ float hdot8(uint4 w, uint4 x) {
    __half2 a = __hmul2(H2(w,0), H2(x,0));
    a = __hfma2(H2(w,1), H2(x,1), a);
    a = __hfma2(H2(w,2), H2(x,2), a);
    a = __hfma2(H2(w,3), H2(x,3), a);
    return __low2float(a) + __high2float(a);
}

__device__ __forceinline__ float wredsum(float v) {
    v += __shfl_xor_sync(0xffffffffu, v, 16);
    v += __shfl_xor_sync(0xffffffffu, v, 8);
    v += __shfl_xor_sync(0xffffffffu, v, 4);
    v += __shfl_xor_sync(0xffffffffu, v, 2);
    v += __shfl_xor_sync(0xffffffffu, v, 1);
    return v;
}

__device__ __forceinline__ float sigf(float x) {
    return __fdividef(1.f, 1.f + __expf(-x));
}
__device__ __forceinline__ float tanhfast(float x) {
    return 2.f * sigf(2.f * x) - 1.f;
}

// round-4 gate dots (smem or ldg). block (g,cp): w + g*GS + cp*64 (64 uint4).
template <int NPAIR, int GS, bool RES>
__device__ __forceinline__ void gatedot4(const uint4* __restrict__ w,
                                         const uint4* __restrict__ xs, int lane, float* a)
{
#pragma unroll
    for (int cp = 0; cp < NPAIR; ++cp) {
        uint4 xa = xs[cp*64 + lane];
        uint4 xb = xs[cp*64 + 32 + lane];
#pragma unroll
        for (int g = 0; g < 4; ++g) {
            uint4 wa = RES ? w[g*GS + cp*64 + lane]      : __ldg(w + g*GS + cp*64 + lane);
            uint4 wb = RES ? w[g*GS + cp*64 + 32 + lane] : __ldg(w + g*GS + cp*64 + 32 + lane);
            a[g] += hdot16(wa, wb, xa, xb);
        }
    }
}

__device__ __forceinline__ void carrive(unsigned* c) {
    asm volatile("red.release.gpu.global.add.u32 [%0], %1;" :: "l"(c), "r"(1u) : "memory");
}
__device__ __forceinline__ void cpoll(unsigned* c, unsigned tgt) {
    unsigned v;
    do {
        asm volatile("ld.acquire.gpu.global.u32 %0, [%1];" : "=r"(v) : "l"(c) : "memory");
    } while ((int)(v - tgt) < 0);
}

// ---- single fused kernel: prep + init + decoupled 4-group pipeline ----
__global__ void __launch_bounds__(NTHREADS, 1) k_all(
    const float* __restrict__ z,
    const float* __restrict__ wih,
    const float* __restrict__ whh,
    const float* __restrict__ bih,
    const float* __restrict__ bhh,
    const float* __restrict__ ws,
    const float* __restrict__ bs,
    const float* __restrict__ wp,
    const float* __restrict__ bp,
    float* __restrict__ dout)
{
    extern __shared__ __align__(16) uint4 smem4[];
    __shared__ unsigned s_pb, s_cb[4];

    const int tid  = threadIdx.x;
    const int bid  = blockIdx.x;
    const int wid  = tid >> 5;
    const int lane = tid & 31;
    const int gtid = bid * NTHREADS + tid;
    const int grp  = bid / GCTAS;          // layer group 0..3
    const int gcta = bid % GCTAS;

    unsigned* cs[4] = {&g_c0, &g_c1, &g_c2, &g_c3};

    // read monotonic counter bases BEFORE any arrival this launch.
    // per-launch deltas: g_pinit += NCTA; each g_c* += TSTEPS*GCTAS (=3737).
    // any pre-read races are bounded far below those periods (see analysis).
    if (tid == 0) {
        unsigned v;
        asm volatile("ld.relaxed.gpu.global.u32 %0, [%1];" : "=r"(v) : "l"(&g_pinit) : "memory");
        s_pb = v - (v % (unsigned)NCTA);
#pragma unroll
        for (int q = 0; q < 4; ++q) {
            asm volatile("ld.relaxed.gpu.global.u32 %0, [%1];" : "=r"(v) : "l"(cs[q]) : "memory");
            s_cb[q] = v - (v % (unsigned)(TSTEPS * GCTAS));
        }
    }

    // ---- prep: pack [Whh|Wih] per gate row, fp32->fp16 (proven in R10) ----
    for (int row = bid; row < NUNITS*4; row += NCTA) {
        if (tid < 512) {
            int half = tid >> 8;
            int k = (tid & 255) * 4;
            int uu = row >> 2, g = row & 3;
            int ll = uu >> 10, jj = uu & 1023;
            size_t src = ((size_t)ll*4096 + g*1024 + jj) * 1024 + k;
            const float* sp = half ? wih : whh;
            float4 v = *(const float4*)(sp + src);
            __half2* d = (__half2*)(g_wpack + (size_t)row * ROWLEN + half*1024 + k);
            d[0] = __floats2half2_rn(v.x, v.y);
            d[1] = __floats2half2_rn(v.z, v.w);
        }
    }
    for (int i = gtid; i < NLAY*4*NHID; i += NCTA*NTHREADS) g_bias[i] = bih[i] + bhh[i];
    for (int i = gtid; i < NST*NHID;    i += NCTA*NTHREADS) g_ws[i] = __float2half_rn(ws[i]);
    for (int i = gtid; i < 2*NLAY*NHID; i += NCTA*NTHREADS) ((__half*)g_hout)[i] = __float2half(0.f);
    if (gtid < TSTEPS) dout[OUT_SAMP + gtid] = (gtid == TSTEPS-1) ? 1.f : 0.f;
    if (gtid == 0) {
        dout[OUT_PROBS + 2*(TSTEPS-1) + 0] = 0.f;
        dout[OUT_PROBS + 2*(TSTEPS-1) + 1] = 1.f;
    }

    // ---- init barrier (global, once): weights + zeroed h visible ----
    __syncthreads();
    if (tid == 0) {
        carrive(&g_pinit);
        cpoll(&g_pinit, s_pb + (unsigned)NCTA);
    }
    __syncthreads();

    // ---- unit ownership ----
    const int uj = gcta * 28 + wid;                 // unit index within layer
    const bool valid = (uj < NHID);
    const int u = grp * NHID + (valid ? uj : 0);
    const uint4* wr4 = (const uint4*)(g_wpack + (size_t)u * 4 * ROWLEN);
    const bool head_warp = (grp == 3) && (gcta == GCTAS-1) && (wid >= 16);

    // resident copies: group 0 -> Whh halves (wid<27); groups 1-3 -> full (wid<13)
    const bool res0 = valid && (grp == 0) && (wid < 27);
    const bool resf = valid && (grp != 0) && (wid < 13);
    if (res0) {
        uint4* dst = smem4 + SW_U4 + wid * 512;
#pragma unroll
        for (int g = 0; g < 4; ++g)
            for (int i = lane; i < 128; i += 32) dst[g*128 + i] = wr4[g*256 + i];
    } else if (resf) {
        uint4* dst = smem4 + SW_U4 + wid * 1024;
#pragma unroll 4
        for (int i = lane; i < 1024; i += 32) dst[i] = wr4[i];
    }
    const uint4* w0sm = smem4 + SW_U4 + wid * 512;
    const uint4* wfsm = smem4 + SW_U4 + wid * 1024;

    float b0 = 0.f, b1 = 0.f, b2 = 0.f, b3 = 0.f;
    if (valid) {
        const float* bl = g_bias + grp*4096 + uj;
        b0 = bl[0]; b1 = bl[1024]; b2 = bl[2048]; b3 = bl[3072];
    }
    float c = 0.f;
    __syncthreads();

    unsigned* c_own  = cs[grp];
    unsigned* c_prev = cs[(grp > 0) ? grp-1 : 0];
    unsigned* c_next = cs[(grp < 3) ? grp+1 : 3];
    const unsigned cb_own  = 0;   // targets computed with s_cb below

    for (int t = 0; t < TSTEPS; ++t) {
        // ---- waits: own t-1 done; producer step t done; consumer step t-2 done ----
        if (tid == 0) {
            if (t >= 1)            cpoll(c_own,  s_cb[grp] + (unsigned)(t * GCTAS));
            if (grp > 0)           cpoll(c_prev, s_cb[grp-1] + (unsigned)((t+1) * GCTAS));
            if (grp < 3 && t >= 2) cpoll(c_next, s_cb[grp+1] + (unsigned)((t-1) * GCTAS));
        }
        __syncthreads();

        // ---- stage: [h_grp(t-1) | x] ; x = h_{grp-1}(t) or z (grp 0, t=0) ----
        if (tid < 128) {
            smem4[tid] = ((const uint4*)&g_hout[(t+1)&1][grp][0])[tid];
        } else if (tid < 256) {
            int k = tid - 128;
            if (grp > 0) {
                smem4[tid] = ((const uint4*)&g_hout[t&1][grp-1][0])[k];
            } else if (t == 0) {
                float4 z0 = ((const float4*)z)[k*2];
                float4 z1 = ((const float4*)z)[k*2 + 1];
                __half2 h0 = __floats2half2_rn(z0.x, z0.y);
                __half2 h1 = __floats2half2_rn(z0.z, z0.w);
                __half2 h2 = __floats2half2_rn(z1.x, z1.y);
                __half2 h3 = __floats2half2_rn(z1.z, z1.w);
                uint4 v;
                v.x = *(unsigned*)&h0; v.y = *(unsigned*)&h1;
                v.z = *(unsigned*)&h2; v.w = *(unsigned*)&h3;
                smem4[tid] = v;
            }
        }
        __syncthreads();

        const uint4* s_x4 = smem4;

        if (valid) {
            float a[4] = {0.f, 0.f, 0.f, 0.f};
            if (grp == 0) {
                if (t == 0)        // gates = Wih * z (h == 0)
                    gatedot4<2,256,false>(wr4 + 128, s_x4 + 128, lane, a);
                else if (res0)     // Whh half from smem
                    gatedot4<2,128,true>(w0sm, s_x4, lane, a);
                else
                    gatedot4<2,256,false>(wr4, s_x4, lane, a);
            } else {
                if (resf) gatedot4<4,256,true>(wfsm, s_x4, lane, a);
                else      gatedot4<4,256,false>(wr4, s_x4, lane, a);
            }
            float gi = wredsum(a[0]) + b0;
            float gf = wredsum(a[1]) + b1;
            float gg = wredsum(a[2]) + b2;
            float go = wredsum(a[3]) + b3;
            c = sigf(gf) * c + sigf(gi) * tanhfast(gg);
            float hn = sigf(go) * tanhfast(c);
            if (lane == 0) g_hout[t&1][grp][uj] = __float2half_rn(hn);
        } else if (head_warp && t >= 1) {
            // heads for step t-1; h_3(t-1) == s_x4[0..127]
            const int th = t - 1;
            for (int r = wid - 16; r < NST + 1; r += 12) {
                if (r < NST) {
                    const uint4* wrow = (const uint4*)(g_ws + r*NHID);
                    float a = 0.f;
#pragma unroll
                    for (int cch = 0; cch < 4; ++cch)
                        a += hdot8(__ldg(wrow + cch*32 + lane), s_x4[cch*32 + lane]);
                    a = wredsum(a);
                    if (lane == 0) dout[OUT_STATES + th*NST + r] = a + bs[r];
                } else {
                    float a0 = 0.f, a1 = 0.f;
#pragma unroll
                    for (int cch = 0; cch < 4; ++cch) {
                        uint4 xv = s_x4[cch*32 + lane];
                        float2 x0 = __half22float2(H2(xv,0));
                        float2 x1 = __half22float2(H2(xv,1));
                        float2 x2 = __half22float2(H2(xv,2));
                        float2 x3 = __half22float2(H2(xv,3));
                        const float4* p0 = (const float4*)(wp) + cch*64 + lane*2;
                        const float4* p1 = (const float4*)(wp + NHID) + cch*64 + lane*2;
                        float4 wA = p0[0], wB = p0[1];
                        float4 wC = p1[0], wD = p1[1];
                        a0 += wA.x*x0.x + wA.y*x0.y + wA.z*x1.x + wA.w*x1.y
                            + wB.x*x2.x + wB.y*x2.y + wB.z*x3.x + wB.w*x3.y;
                        a1 += wC.x*x0.x + wC.y*x0.y + wC.z*x1.x + wC.w*x1.y
                            + wD.x*x2.x + wD.y*x2.y + wD.z*x3.x + wD.w*x3.y;
                    }
                    a0 = wredsum(a0); a1 = wredsum(a1);
                    if (lane == 0) {
                        float l0v = a0 + bp[0] + 1.0f;   // P_BIAS on logit 0
                        float l1v = a1 + bp[1];
                        float m  = fmaxf(l0v, l1v);
                        float e0 = __expf(l0v - m), e1 = __expf(l1v - m);
                        float inv = 1.f / (e0 + e1);
                        dout[OUT_PROBS + th*2 + 0] = e0 * inv;
                        dout[OUT_PROBS + th*2 + 1] = e1 * inv;
                    }
                }
            }
        }

        // ---- arrive: this CTA finished step t ----
        __syncthreads();
        if (tid == 0) carrive(c_own);
    }

    // ---- epilogue: states for t=100 (head CTA only) ----
    if (grp == 3 && gcta == GCTAS-1) {
        if (tid == 0) cpoll(&g_c3, s_cb[3] + (unsigned)(TSTEPS * GCTAS));
        __syncthreads();
        if (wid >= 16) {
            const uint4* xs = (const uint4*)(&g_hout[(TSTEPS-1)&1][3][0]);
            for (int r = wid - 16; r < NST; r += 12) {
                const uint4* wrow = (const uint4*)(g_ws + r*NHID);
                float a = 0.f;
#pragma unroll
                for (int cch = 0; cch < 4; ++cch)
                    a += hdot8(__ldg(wrow + cch*32 + lane), xs[cch*32 + lane]);
                a = wredsum(a);
                if (lane == 0) dout[OUT_STATES + (TSTEPS-1)*NST + r] = a + bs[r];
            }
        }
    }
}

extern "C" void kernel_launch(void* const* d_in, const int* in_sizes, int n_in,
                              void* d_out, int out_size) {
    (void)in_sizes; (void)n_in; (void)out_size;
    const float* z   = (const float*)d_in[0];
    const float* wih = (const float*)d_in[1];
    const float* whh = (const float*)d_in[2];
    const float* bih = (const float*)d_in[3];
    const float* bhh = (const float*)d_in[4];
    const float* ws  = (const float*)d_in[5];
    const float* bs  = (const float*)d_in[6];
    const float* wp  = (const float*)d_in[7];
    const float* bp  = (const float*)d_in[8];
    float* out = (float*)d_out;

    cudaFuncSetAttribute(k_all, cudaFuncAttributeMaxDynamicSharedMemorySize, SMEM_TOTAL);
    k_all<<<NCTA, NTHREADS, SMEM_TOTAL>>>(z, wih, whh, bih, bhh, ws, bs, wp, bp, out);
}